// round 1
// baseline (speedup 1.0000x reference)
#include <cuda_runtime.h>

#define BSZ   2
#define SEQ   2048
#define DMODEL 1024
#define NHEAD 16
#define DKH   64
#define MROWS (BSZ * SEQ)   // 4096

// Scratch (allocation-free rule: __device__ globals)
__device__ float g_q[MROWS * DMODEL];
__device__ float g_k[MROWS * DMODEL];
__device__ float g_v[MROWS * DMODEL];
__device__ float g_a[MROWS * DMODEL];

// ---------------------------------------------------------------------------
// SGEMM NT: C[m,n] = sum_k A[m,k] * W[n,k]   (x @ W.T)
// 128x128 block, BK=8, 256 threads, 8x8 micro-tile per thread.
// ---------------------------------------------------------------------------
__global__ __launch_bounds__(256) void sgemm_nt(
    const float* __restrict__ A, const float* __restrict__ W,
    float* __restrict__ C, int M, int N, int K)
{
    __shared__ float As[8][128];
    __shared__ float Bs[8][128];

    const int tid = threadIdx.x;
    const int tx = tid & 15;        // 0..15 -> N micro
    const int ty = tid >> 4;        // 0..15 -> M micro
    const int m0 = blockIdx.y * 128;
    const int n0 = blockIdx.x * 128;

    const int lrow = tid >> 1;          // 0..127
    const int lk   = (tid & 1) << 2;    // 0 or 4

    const float* Ap = A + (size_t)(m0 + lrow) * K + lk;
    const float* Wp = W + (size_t)(n0 + lrow) * K + lk;

    float acc[8][8];
#pragma unroll
    for (int i = 0; i < 8; i++)
#pragma unroll
        for (int j = 0; j < 8; j++) acc[i][j] = 0.0f;

    for (int k0 = 0; k0 < K; k0 += 8) {
        float4 a4 = *(const float4*)(Ap + k0);
        float4 b4 = *(const float4*)(Wp + k0);
        As[lk + 0][lrow] = a4.x; As[lk + 1][lrow] = a4.y;
        As[lk + 2][lrow] = a4.z; As[lk + 3][lrow] = a4.w;
        Bs[lk + 0][lrow] = b4.x; Bs[lk + 1][lrow] = b4.y;
        Bs[lk + 2][lrow] = b4.z; Bs[lk + 3][lrow] = b4.w;
        __syncthreads();

#pragma unroll
        for (int kk = 0; kk < 8; kk++) {
            float ar[8], br[8];
#pragma unroll
            for (int i = 0; i < 8; i++) ar[i] = As[kk][ty * 8 + i];
#pragma unroll
            for (int j = 0; j < 8; j++) br[j] = Bs[kk][tx * 8 + j];
#pragma unroll
            for (int i = 0; i < 8; i++)
#pragma unroll
                for (int j = 0; j < 8; j++)
                    acc[i][j] = fmaf(ar[i], br[j], acc[i][j]);
        }
        __syncthreads();
    }

#pragma unroll
    for (int i = 0; i < 8; i++) {
        const int m = m0 + ty * 8 + i;
        float4* crow = (float4*)(C + (size_t)m * N + n0 + tx * 8);
        crow[0] = make_float4(acc[i][0], acc[i][1], acc[i][2], acc[i][3]);
        crow[1] = make_float4(acc[i][4], acc[i][5], acc[i][6], acc[i][7]);
    }
}

// ---------------------------------------------------------------------------
// Flash attention (fp32, causal), per block: one (b,h) and 64 query rows.
// BQ = BKV = dk = 64. 256 threads, 4x4 micro-tiles, online softmax.
// Layout of q/k/v/out buffers: [B, S, H*dk] (head h at columns h*64..h*64+63).
// ---------------------------------------------------------------------------
__global__ __launch_bounds__(256) void flash_attn(
    const float* __restrict__ Q, const float* __restrict__ Kt,
    const float* __restrict__ Vt, float* __restrict__ O)
{
    extern __shared__ float sm[];
    const int LD = 68;               // padded row stride
    float* Qs = sm;                  // [64][68]
    float* Ks = Qs + 64 * LD;
    float* Vs = Ks + 64 * LD;
    float* Ps = Vs + 64 * LD;

    const int tid = threadIdx.x;
    const int tx = tid & 15;
    const int ty = tid >> 4;
    const int qb = blockIdx.x;
    const int h  = blockIdx.y;
    const int b  = blockIdx.z;
    const int q0 = qb * 64;

    const size_t base = (size_t)b * SEQ * DMODEL + (size_t)h * DKH;

    // Load Q tile [64, 64]
    for (int i = tid; i < 64 * 16; i += 256) {
        const int r = i >> 4;
        const int c = (i & 15) << 2;
        float4 t = *(const float4*)(Q + base + (size_t)(q0 + r) * DMODEL + c);
        Qs[r * LD + c + 0] = t.x; Qs[r * LD + c + 1] = t.y;
        Qs[r * LD + c + 2] = t.z; Qs[r * LD + c + 3] = t.w;
    }

    float m_i[4], l_i[4], acc[4][4];
#pragma unroll
    for (int i = 0; i < 4; i++) {
        m_i[i] = -1e30f; l_i[i] = 0.0f;
#pragma unroll
        for (int j = 0; j < 4; j++) acc[i][j] = 0.0f;
    }

    for (int kb = 0; kb <= qb; kb++) {
        const int k0 = kb * 64;
        __syncthreads();  // prior iter done with Ks/Vs/Ps; Q tile visible on iter 0

        // Load K, V tiles [64, 64]
        for (int i = tid; i < 64 * 16; i += 256) {
            const int r = i >> 4;
            const int c = (i & 15) << 2;
            float4 t = *(const float4*)(Kt + base + (size_t)(k0 + r) * DMODEL + c);
            Ks[r * LD + c + 0] = t.x; Ks[r * LD + c + 1] = t.y;
            Ks[r * LD + c + 2] = t.z; Ks[r * LD + c + 3] = t.w;
            float4 u = *(const float4*)(Vt + base + (size_t)(k0 + r) * DMODEL + c);
            Vs[r * LD + c + 0] = u.x; Vs[r * LD + c + 1] = u.y;
            Vs[r * LD + c + 2] = u.z; Vs[r * LD + c + 3] = u.w;
        }
        __syncthreads();

        // S = Q @ K^T for this tile, 4x4 per thread
        float s[4][4];
#pragma unroll
        for (int i = 0; i < 4; i++)
#pragma unroll
            for (int j = 0; j < 4; j++) s[i][j] = 0.0f;

#pragma unroll 8
        for (int d = 0; d < 64; d++) {
            float ar[4], br[4];
#pragma unroll
            for (int i = 0; i < 4; i++) ar[i] = Qs[(ty * 4 + i) * LD + d];
#pragma unroll
            for (int j = 0; j < 4; j++) br[j] = Ks[(tx * 4 + j) * LD + d];
#pragma unroll
            for (int i = 0; i < 4; i++)
#pragma unroll
                for (int j = 0; j < 4; j++)
                    s[i][j] = fmaf(ar[i], br[j], s[i][j]);
        }

        const bool diag = (kb == qb);
#pragma unroll
        for (int i = 0; i < 4; i++)
#pragma unroll
            for (int j = 0; j < 4; j++) {
                s[i][j] *= 0.125f;   // 1/sqrt(64)
                if (diag && (k0 + tx * 4 + j > q0 + ty * 4 + i))
                    s[i][j] = -1e30f;
            }

        // Online softmax update per row (rows spread across 16 lanes of tx)
#pragma unroll
        for (int i = 0; i < 4; i++) {
            float rm = fmaxf(fmaxf(s[i][0], s[i][1]), fmaxf(s[i][2], s[i][3]));
#pragma unroll
            for (int off = 1; off < 16; off <<= 1)
                rm = fmaxf(rm, __shfl_xor_sync(0xffffffffu, rm, off));
            const float mn = fmaxf(m_i[i], rm);
            const float alpha = __expf(m_i[i] - mn);
            m_i[i] = mn;
            float rs = 0.0f;
#pragma unroll
            for (int j = 0; j < 4; j++) {
                s[i][j] = __expf(s[i][j] - mn);
                rs += s[i][j];
            }
#pragma unroll
            for (int off = 1; off < 16; off <<= 1)
                rs += __shfl_xor_sync(0xffffffffu, rs, off);
            l_i[i] = l_i[i] * alpha + rs;
#pragma unroll
            for (int j = 0; j < 4; j++) {
                acc[i][j] *= alpha;
                Ps[(ty * 4 + i) * LD + tx * 4 + j] = s[i][j];
            }
        }
        __syncthreads();

        // O += P @ V
#pragma unroll 8
        for (int d = 0; d < 64; d++) {
            float ar[4], br[4];
#pragma unroll
            for (int i = 0; i < 4; i++) ar[i] = Ps[(ty * 4 + i) * LD + d];
#pragma unroll
            for (int j = 0; j < 4; j++) br[j] = Vs[d * LD + tx * 4 + j];
#pragma unroll
            for (int i = 0; i < 4; i++)
#pragma unroll
                for (int j = 0; j < 4; j++)
                    acc[i][j] = fmaf(ar[i], br[j], acc[i][j]);
        }
    }

    // Normalize and write out
#pragma unroll
    for (int i = 0; i < 4; i++) {
        const float inv = 1.0f / l_i[i];
#pragma unroll
        for (int j = 0; j < 4; j++) {
            O[base + (size_t)(q0 + ty * 4 + i) * DMODEL + tx * 4 + j] =
                acc[i][j] * inv;
        }
    }
}

// ---------------------------------------------------------------------------
// Launch
// ---------------------------------------------------------------------------
extern "C" void kernel_launch(void* const* d_in, const int* in_sizes, int n_in,
                              void* d_out, int out_size)
{
    const float* x  = (const float*)d_in[0];
    const float* Wq = (const float*)d_in[1];
    const float* Wk = (const float*)d_in[2];
    const float* Wv = (const float*)d_in[3];
    const float* Wo = (const float*)d_in[4];
    float* out = (float*)d_out;

    float *qb, *kb, *vb, *ab;
    cudaGetSymbolAddress((void**)&qb, g_q);
    cudaGetSymbolAddress((void**)&kb, g_k);
    cudaGetSymbolAddress((void**)&vb, g_v);
    cudaGetSymbolAddress((void**)&ab, g_a);

    const dim3 gemm_grid(DMODEL / 128, MROWS / 128);  // (8, 32)

    sgemm_nt<<<gemm_grid, 256>>>(x, Wq, qb, MROWS, DMODEL, DMODEL);
    sgemm_nt<<<gemm_grid, 256>>>(x, Wk, kb, MROWS, DMODEL, DMODEL);
    sgemm_nt<<<gemm_grid, 256>>>(x, Wv, vb, MROWS, DMODEL, DMODEL);

    const int smem = 4 * 64 * 68 * (int)sizeof(float);  // 69632 B
    cudaFuncSetAttribute(flash_attn,
                         cudaFuncAttributeMaxDynamicSharedMemorySize, smem);
    flash_attn<<<dim3(SEQ / 64, NHEAD, BSZ), 256, smem>>>(qb, kb, vb, ab);

    sgemm_nt<<<gemm_grid, 256>>>(ab, Wo, out, MROWS, DMODEL, DMODEL);
}

// round 3
// speedup vs baseline: 1.4131x; 1.4131x over previous
#include <cuda_runtime.h>
#include <cstdint>

#define BSZ    2
#define SEQ    2048
#define DMODEL 1024
#define NHEAD  16
#define DKH    64
#define MROWS  (BSZ * SEQ)   // 4096

// Scratch (allocation-free rule: __device__ globals)
__device__ float g_q[MROWS * DMODEL];
__device__ float g_k[MROWS * DMODEL];
__device__ float g_v[MROWS * DMODEL];
__device__ float g_a[MROWS * DMODEL];

// ---------------------------------------------------------------------------
// tf32 helpers (sm_80+ features only — the build targets plain sm_103)
// ---------------------------------------------------------------------------
__device__ __forceinline__ uint32_t tf32_rn(float x) {
    uint32_t u;
    asm("cvt.rna.tf32.f32 %0, %1;" : "=r"(u) : "f"(x));
    return u;
}

__device__ __forceinline__ void mma_tf32(
    float& d0, float& d1, float& d2, float& d3,
    uint32_t a0, uint32_t a1, uint32_t a2, uint32_t a3,
    uint32_t b0, uint32_t b1)
{
    asm volatile(
        "mma.sync.aligned.m16n8k8.row.col.f32.tf32.tf32.f32 "
        "{%0,%1,%2,%3}, {%4,%5,%6,%7}, {%8,%9}, {%0,%1,%2,%3};"
        : "+f"(d0), "+f"(d1), "+f"(d2), "+f"(d3)
        : "r"(a0), "r"(a1), "r"(a2), "r"(a3), "r"(b0), "r"(b1));
}

// ---------------------------------------------------------------------------
// tf32 GEMM NT: C[m,n] = sum_k A[m,k] * W[n,k]   (M=4096, N=K=1024)
//
// CTA: 256 threads (8 warps), tile 128Mx128N, BK=32, double-buffered smem.
// Warp grid 4(M)x2(N): each warp 32Mx64N = 2 m-tiles x 8 n-tiles of m16n8k8.
//
// Smem holds operands in FRAGMENT-PERMUTED order:
//   A_frag[ks<4][mt<8][lane<32][reg<4]  (one LDS.128 per (mt,ks) per lane)
//   B_frag[ks<4][nt<16][lane<32][reg<2] (one LDS.64  per (nt,ks) per lane)
// mma.m16n8k8 tf32 fragment maps (PTX ISA): lane l: g=l>>2, q=l&3.
//   A: a0=(g,q) a1=(g+8,q) a2=(g,q+4) a3=(g+8,q+4)
//   B: b0=(k=q,n=g) b1=(k=q+4,n=g)
//   D: c0=(g,2q) c1=(g,2q+1) c2=(g+8,2q) c3=(g+8,2q+1)
// ---------------------------------------------------------------------------
#define STAGE_FLOATS 8192            // 16KB A-frags + 16KB B-frags = 8192 floats
#define GEMM_SMEM    (2 * STAGE_FLOATS * 4)   // 65536 B

__global__ __launch_bounds__(256, 1) void gemm_tf32(
    const float* __restrict__ A, const float* __restrict__ W, float* __restrict__ C)
{
    extern __shared__ float smf[];

    const int tid  = threadIdx.x;
    const int wid  = tid >> 5;
    const int lane = tid & 31;
    const int wm   = wid & 3;        // warp M group (0..3)
    const int wn   = wid >> 2;       // warp N group (0..1)
    const int m0 = blockIdx.y * 128;
    const int n0 = blockIdx.x * 128;

    // Loader coordinates
    const int lrow  = tid >> 3;          // 0..31
    const int cbase = (tid & 7) * 4;     // 0,4,...,28 (k offset within chunk)
    const int ks_w  = cbase >> 3;        // kstep of this loader column
    const int half  = (cbase >> 2) & 1;  // 0 or 1

    float acc[2][8][4];
#pragma unroll
    for (int i = 0; i < 2; i++)
#pragma unroll
        for (int j = 0; j < 8; j++)
#pragma unroll
            for (int r = 0; r < 4; r++) acc[i][j][r] = 0.0f;

    float4 av[4], bv[4];

    // --- prologue: fetch chunk 0 ---
#pragma unroll
    for (int it = 0; it < 4; it++) {
        av[it] = *(const float4*)(A + (size_t)(m0 + it * 32 + lrow) * DMODEL + cbase);
        bv[it] = *(const float4*)(W + (size_t)(n0 + it * 32 + lrow) * DMODEL + cbase);
    }

    const int NCHUNK = DMODEL / 32;  // 32

    for (int s = 0; s < NCHUNK; s++) {
        // --- store staged regs into fragment-permuted smem (stage s&1) ---
        {
            float* sa = smf + (s & 1) * STAGE_FLOATS;         // A frags
            float* sb = sa + 4096;                            // B frags
#pragma unroll
            for (int it = 0; it < 4; it++) {
                const int r  = it * 32 + lrow;
                // A: element (r, cbase+j)
                const int mt = r >> 4, rr = r & 15, ga = rr & 7, hi = rr >> 3;
                const int fa = ((ks_w * 8 + mt) * 32 + ga * 4) * 4 + (hi + 2 * half);
                sa[fa + 0]  = __uint_as_float(tf32_rn(av[it].x));
                sa[fa + 4]  = __uint_as_float(tf32_rn(av[it].y));
                sa[fa + 8]  = __uint_as_float(tf32_rn(av[it].z));
                sa[fa + 12] = __uint_as_float(tf32_rn(av[it].w));
                // B: element (n=r, k=cbase+j)
                const int nt = r >> 3, gb = r & 7;
                const int fb = ((ks_w * 16 + nt) * 32 + gb * 4) * 2 + half;
                sb[fb + 0] = __uint_as_float(tf32_rn(bv[it].x));
                sb[fb + 2] = __uint_as_float(tf32_rn(bv[it].y));
                sb[fb + 4] = __uint_as_float(tf32_rn(bv[it].z));
                sb[fb + 6] = __uint_as_float(tf32_rn(bv[it].w));
            }
        }
        __syncthreads();

        // --- prefetch next chunk while computing this one ---
        if (s + 1 < NCHUNK) {
            const int kc = (s + 1) * 32 + cbase;
#pragma unroll
            for (int it = 0; it < 4; it++) {
                av[it] = *(const float4*)(A + (size_t)(m0 + it * 32 + lrow) * DMODEL + kc);
                bv[it] = *(const float4*)(W + (size_t)(n0 + it * 32 + lrow) * DMODEL + kc);
            }
        }

        // --- compute on stage s&1 ---
        {
            const float* sa = smf + (s & 1) * STAGE_FLOATS;
            const float* sb = sa + 4096;
#pragma unroll
            for (int ks = 0; ks < 4; ks++) {
                uint4 af[2];
                uint2 bf[8];
#pragma unroll
                for (int mt = 0; mt < 2; mt++)
                    af[mt] = *(const uint4*)(sa + ((ks * 8 + wm * 2 + mt) * 32 + lane) * 4);
#pragma unroll
                for (int nt = 0; nt < 8; nt++)
                    bf[nt] = *(const uint2*)(sb + ((ks * 16 + wn * 8 + nt) * 32 + lane) * 2);
#pragma unroll
                for (int mt = 0; mt < 2; mt++)
#pragma unroll
                    for (int nt = 0; nt < 8; nt++)
                        mma_tf32(acc[mt][nt][0], acc[mt][nt][1],
                                 acc[mt][nt][2], acc[mt][nt][3],
                                 af[mt].x, af[mt].y, af[mt].z, af[mt].w,
                                 bf[nt].x, bf[nt].y);
            }
        }
        __syncthreads();   // all warps done with stage s&1 before it is overwritten
    }

    // --- epilogue: D frags straight to global (float2 per half-tile) ---
    const int g = lane >> 2, q = lane & 3;
#pragma unroll
    for (int mt = 0; mt < 2; mt++) {
        const int mrow = m0 + wm * 32 + mt * 16 + g;
#pragma unroll
        for (int nt = 0; nt < 8; nt++) {
            const int ncol = n0 + wn * 64 + nt * 8 + 2 * q;
            *(float2*)(C + (size_t)mrow * DMODEL + ncol) =
                make_float2(acc[mt][nt][0], acc[mt][nt][1]);
            *(float2*)(C + (size_t)(mrow + 8) * DMODEL + ncol) =
                make_float2(acc[mt][nt][2], acc[mt][nt][3]);
        }
    }
}

// ---------------------------------------------------------------------------
// Flash attention (fp32, causal) — unchanged (verified round 1).
// ---------------------------------------------------------------------------
__global__ __launch_bounds__(256) void flash_attn(
    const float* __restrict__ Q, const float* __restrict__ Kt,
    const float* __restrict__ Vt, float* __restrict__ O)
{
    extern __shared__ float sm[];
    const int LD = 68;
    float* Qs = sm;
    float* Ks = Qs + 64 * LD;
    float* Vs = Ks + 64 * LD;
    float* Ps = Vs + 64 * LD;

    const int tid = threadIdx.x;
    const int tx = tid & 15;
    const int ty = tid >> 4;
    const int qb = blockIdx.x;
    const int h  = blockIdx.y;
    const int b  = blockIdx.z;
    const int q0 = qb * 64;

    const size_t base = (size_t)b * SEQ * DMODEL + (size_t)h * DKH;

    for (int i = tid; i < 64 * 16; i += 256) {
        const int r = i >> 4;
        const int c = (i & 15) << 2;
        float4 t = *(const float4*)(Q + base + (size_t)(q0 + r) * DMODEL + c);
        Qs[r * LD + c + 0] = t.x; Qs[r * LD + c + 1] = t.y;
        Qs[r * LD + c + 2] = t.z; Qs[r * LD + c + 3] = t.w;
    }

    float m_i[4], l_i[4], acc[4][4];
#pragma unroll
    for (int i = 0; i < 4; i++) {
        m_i[i] = -1e30f; l_i[i] = 0.0f;
#pragma unroll
        for (int j = 0; j < 4; j++) acc[i][j] = 0.0f;
    }

    for (int kb = 0; kb <= qb; kb++) {
        const int k0 = kb * 64;
        __syncthreads();

        for (int i = tid; i < 64 * 16; i += 256) {
            const int r = i >> 4;
            const int c = (i & 15) << 2;
            float4 t = *(const float4*)(Kt + base + (size_t)(k0 + r) * DMODEL + c);
            Ks[r * LD + c + 0] = t.x; Ks[r * LD + c + 1] = t.y;
            Ks[r * LD + c + 2] = t.z; Ks[r * LD + c + 3] = t.w;
            float4 u = *(const float4*)(Vt + base + (size_t)(k0 + r) * DMODEL + c);
            Vs[r * LD + c + 0] = u.x; Vs[r * LD + c + 1] = u.y;
            Vs[r * LD + c + 2] = u.z; Vs[r * LD + c + 3] = u.w;
        }
        __syncthreads();

        float s[4][4];
#pragma unroll
        for (int i = 0; i < 4; i++)
#pragma unroll
            for (int j = 0; j < 4; j++) s[i][j] = 0.0f;

#pragma unroll 8
        for (int d = 0; d < 64; d++) {
            float ar[4], br[4];
#pragma unroll
            for (int i = 0; i < 4; i++) ar[i] = Qs[(ty * 4 + i) * LD + d];
#pragma unroll
            for (int j = 0; j < 4; j++) br[j] = Ks[(tx * 4 + j) * LD + d];
#pragma unroll
            for (int i = 0; i < 4; i++)
#pragma unroll
                for (int j = 0; j < 4; j++)
                    s[i][j] = fmaf(ar[i], br[j], s[i][j]);
        }

        const bool diag = (kb == qb);
#pragma unroll
        for (int i = 0; i < 4; i++)
#pragma unroll
            for (int j = 0; j < 4; j++) {
                s[i][j] *= 0.125f;
                if (diag && (k0 + tx * 4 + j > q0 + ty * 4 + i))
                    s[i][j] = -1e30f;
            }

#pragma unroll
        for (int i = 0; i < 4; i++) {
            float rm = fmaxf(fmaxf(s[i][0], s[i][1]), fmaxf(s[i][2], s[i][3]));
#pragma unroll
            for (int off = 1; off < 16; off <<= 1)
                rm = fmaxf(rm, __shfl_xor_sync(0xffffffffu, rm, off));
            const float mn = fmaxf(m_i[i], rm);
            const float alpha = __expf(m_i[i] - mn);
            m_i[i] = mn;
            float rs = 0.0f;
#pragma unroll
            for (int j = 0; j < 4; j++) {
                s[i][j] = __expf(s[i][j] - mn);
                rs += s[i][j];
            }
#pragma unroll
            for (int off = 1; off < 16; off <<= 1)
                rs += __shfl_xor_sync(0xffffffffu, rs, off);
            l_i[i] = l_i[i] * alpha + rs;
#pragma unroll
            for (int j = 0; j < 4; j++) {
                acc[i][j] *= alpha;
                Ps[(ty * 4 + i) * LD + tx * 4 + j] = s[i][j];
            }
        }
        __syncthreads();

#pragma unroll 8
        for (int d = 0; d < 64; d++) {
            float ar[4], br[4];
#pragma unroll
            for (int i = 0; i < 4; i++) ar[i] = Ps[(ty * 4 + i) * LD + d];
#pragma unroll
            for (int j = 0; j < 4; j++) br[j] = Vs[d * LD + tx * 4 + j];
#pragma unroll
            for (int i = 0; i < 4; i++)
#pragma unroll
                for (int j = 0; j < 4; j++)
                    acc[i][j] = fmaf(ar[i], br[j], acc[i][j]);
        }
    }

#pragma unroll
    for (int i = 0; i < 4; i++) {
        const float inv = 1.0f / l_i[i];
#pragma unroll
        for (int j = 0; j < 4; j++) {
            O[base + (size_t)(q0 + ty * 4 + i) * DMODEL + tx * 4 + j] =
                acc[i][j] * inv;
        }
    }
}

// ---------------------------------------------------------------------------
// Launch
// ---------------------------------------------------------------------------
extern "C" void kernel_launch(void* const* d_in, const int* in_sizes, int n_in,
                              void* d_out, int out_size)
{
    const float* x  = (const float*)d_in[0];
    const float* Wq = (const float*)d_in[1];
    const float* Wk = (const float*)d_in[2];
    const float* Wv = (const float*)d_in[3];
    const float* Wo = (const float*)d_in[4];
    float* out = (float*)d_out;

    float *qb, *kb, *vb, *ab;
    cudaGetSymbolAddress((void**)&qb, g_q);
    cudaGetSymbolAddress((void**)&kb, g_k);
    cudaGetSymbolAddress((void**)&vb, g_v);
    cudaGetSymbolAddress((void**)&ab, g_a);

    cudaFuncSetAttribute(gemm_tf32,
                         cudaFuncAttributeMaxDynamicSharedMemorySize, GEMM_SMEM);

    const dim3 gemm_grid(DMODEL / 128, MROWS / 128);  // (8, 32)
    gemm_tf32<<<gemm_grid, 256, GEMM_SMEM>>>(x, Wq, qb);
    gemm_tf32<<<gemm_grid, 256, GEMM_SMEM>>>(x, Wk, kb);
    gemm_tf32<<<gemm_grid, 256, GEMM_SMEM>>>(x, Wv, vb);

    const int fa_smem = 4 * 64 * 68 * (int)sizeof(float);  // 69632
    cudaFuncSetAttribute(flash_attn,
                         cudaFuncAttributeMaxDynamicSharedMemorySize, fa_smem);
    flash_attn<<<dim3(SEQ / 64, NHEAD, BSZ), 256, fa_smem>>>(qb, kb, vb, ab);

    gemm_tf32<<<gemm_grid, 256, GEMM_SMEM>>>(ab, Wo, out);
}

// round 4
// speedup vs baseline: 2.7432x; 1.9413x over previous
#include <cuda_runtime.h>
#include <cstdint>

#define BSZ    2
#define SEQ    2048
#define DMODEL 1024
#define NHEAD  16
#define DKH    64
#define MROWS  (BSZ * SEQ)   // 4096

// Scratch (allocation-free rule: __device__ globals)
__device__ float g_q[MROWS * DMODEL];
__device__ float g_k[MROWS * DMODEL];
__device__ float g_v[MROWS * DMODEL];
__device__ float g_a[MROWS * DMODEL];

// ---------------------------------------------------------------------------
// tf32 helpers (sm_80+ features only — the build targets plain sm_103)
// ---------------------------------------------------------------------------
__device__ __forceinline__ uint32_t tf32_rn(float x) {
    uint32_t u;
    asm("cvt.rna.tf32.f32 %0, %1;" : "=r"(u) : "f"(x));
    return u;
}

__device__ __forceinline__ void mma_tf32(
    float& d0, float& d1, float& d2, float& d3,
    uint32_t a0, uint32_t a1, uint32_t a2, uint32_t a3,
    uint32_t b0, uint32_t b1)
{
    asm volatile(
        "mma.sync.aligned.m16n8k8.row.col.f32.tf32.tf32.f32 "
        "{%0,%1,%2,%3}, {%4,%5,%6,%7}, {%8,%9}, {%0,%1,%2,%3};"
        : "+f"(d0), "+f"(d1), "+f"(d2), "+f"(d3)
        : "r"(a0), "r"(a1), "r"(a2), "r"(a3), "r"(b0), "r"(b1));
}

// ---------------------------------------------------------------------------
// tf32 GEMM NT: C[m,n] = sum_k A[m,k] * W[n,k]   (validated round 3)
// ---------------------------------------------------------------------------
#define STAGE_FLOATS 8192
#define GEMM_SMEM    (2 * STAGE_FLOATS * 4)   // 65536 B

__global__ __launch_bounds__(256, 1) void gemm_tf32(
    const float* __restrict__ A, const float* __restrict__ W, float* __restrict__ C)
{
    extern __shared__ float smf[];

    const int tid  = threadIdx.x;
    const int wid  = tid >> 5;
    const int lane = tid & 31;
    const int wm   = wid & 3;
    const int wn   = wid >> 2;
    const int m0 = blockIdx.y * 128;
    const int n0 = blockIdx.x * 128;

    const int lrow  = tid >> 3;
    const int cbase = (tid & 7) * 4;
    const int ks_w  = cbase >> 3;
    const int half  = (cbase >> 2) & 1;

    float acc[2][8][4];
#pragma unroll
    for (int i = 0; i < 2; i++)
#pragma unroll
        for (int j = 0; j < 8; j++)
#pragma unroll
            for (int r = 0; r < 4; r++) acc[i][j][r] = 0.0f;

    float4 av[4], bv[4];

#pragma unroll
    for (int it = 0; it < 4; it++) {
        av[it] = *(const float4*)(A + (size_t)(m0 + it * 32 + lrow) * DMODEL + cbase);
        bv[it] = *(const float4*)(W + (size_t)(n0 + it * 32 + lrow) * DMODEL + cbase);
    }

    const int NCHUNK = DMODEL / 32;

    for (int s = 0; s < NCHUNK; s++) {
        {
            float* sa = smf + (s & 1) * STAGE_FLOATS;
            float* sb = sa + 4096;
#pragma unroll
            for (int it = 0; it < 4; it++) {
                const int r  = it * 32 + lrow;
                const int mt = r >> 4, rr = r & 15, ga = rr & 7, hi = rr >> 3;
                const int fa = ((ks_w * 8 + mt) * 32 + ga * 4) * 4 + (hi + 2 * half);
                sa[fa + 0]  = __uint_as_float(tf32_rn(av[it].x));
                sa[fa + 4]  = __uint_as_float(tf32_rn(av[it].y));
                sa[fa + 8]  = __uint_as_float(tf32_rn(av[it].z));
                sa[fa + 12] = __uint_as_float(tf32_rn(av[it].w));
                const int nt = r >> 3, gb = r & 7;
                const int fb = ((ks_w * 16 + nt) * 32 + gb * 4) * 2 + half;
                sb[fb + 0] = __uint_as_float(tf32_rn(bv[it].x));
                sb[fb + 2] = __uint_as_float(tf32_rn(bv[it].y));
                sb[fb + 4] = __uint_as_float(tf32_rn(bv[it].z));
                sb[fb + 6] = __uint_as_float(tf32_rn(bv[it].w));
            }
        }
        __syncthreads();

        if (s + 1 < NCHUNK) {
            const int kc = (s + 1) * 32 + cbase;
#pragma unroll
            for (int it = 0; it < 4; it++) {
                av[it] = *(const float4*)(A + (size_t)(m0 + it * 32 + lrow) * DMODEL + kc);
                bv[it] = *(const float4*)(W + (size_t)(n0 + it * 32 + lrow) * DMODEL + kc);
            }
        }

        {
            const float* sa = smf + (s & 1) * STAGE_FLOATS;
            const float* sb = sa + 4096;
#pragma unroll
            for (int ks = 0; ks < 4; ks++) {
                uint4 af[2];
                uint2 bf[8];
#pragma unroll
                for (int mt = 0; mt < 2; mt++)
                    af[mt] = *(const uint4*)(sa + ((ks * 8 + wm * 2 + mt) * 32 + lane) * 4);
#pragma unroll
                for (int nt = 0; nt < 8; nt++)
                    bf[nt] = *(const uint2*)(sb + ((ks * 16 + wn * 8 + nt) * 32 + lane) * 2);
#pragma unroll
                for (int mt = 0; mt < 2; mt++)
#pragma unroll
                    for (int nt = 0; nt < 8; nt++)
                        mma_tf32(acc[mt][nt][0], acc[mt][nt][1],
                                 acc[mt][nt][2], acc[mt][nt][3],
                                 af[mt].x, af[mt].y, af[mt].z, af[mt].w,
                                 bf[nt].x, bf[nt].y);
            }
        }
        __syncthreads();
    }

    const int g = lane >> 2, q = lane & 3;
#pragma unroll
    for (int mt = 0; mt < 2; mt++) {
        const int mrow = m0 + wm * 32 + mt * 16 + g;
#pragma unroll
        for (int nt = 0; nt < 8; nt++) {
            const int ncol = n0 + wn * 64 + nt * 8 + 2 * q;
            *(float2*)(C + (size_t)mrow * DMODEL + ncol) =
                make_float2(acc[mt][nt][0], acc[mt][nt][1]);
            *(float2*)(C + (size_t)(mrow + 8) * DMODEL + ncol) =
                make_float2(acc[mt][nt][2], acc[mt][nt][3]);
        }
    }
}

// ---------------------------------------------------------------------------
// Tensor-core flash attention (tf32 mma.sync, causal).
// BQ=128 (8 warps x m16), BKV=64, dk=64. 256 threads.
// Q held in registers as A-fragments; P stored in warp-private smem rows.
// Smem pads: Ps/Ks = 68 (conflict-free (4g+q)), Vs = 72 (conflict-free (8q+g)).
// ---------------------------------------------------------------------------
#define FA_LDP 68
#define FA_LDK 68
#define FA_LDV 72
#define FA_SMEM ((128 * FA_LDP + 64 * FA_LDK + 64 * FA_LDV) * 4)   // 70656 B

__global__ __launch_bounds__(256, 1) void flash_attn_tc(
    const float* __restrict__ Q, const float* __restrict__ K,
    const float* __restrict__ V, float* __restrict__ O)
{
    extern __shared__ float sm[];
    float* Ps = sm;                       // 128 x 68 (Q staging, then P tiles)
    float* Ks = Ps + 128 * FA_LDP;        // 64 x 68
    float* Vs = Ks + 64 * FA_LDK;         // 64 x 72

    const int tid  = threadIdx.x;
    const int w    = tid >> 5;
    const int lane = tid & 31;
    const int g    = lane >> 2;
    const int q    = lane & 3;
    const int qb = blockIdx.x, h = blockIdx.y, b = blockIdx.z;
    const int q0 = qb * 128;
    const size_t base = (size_t)b * SEQ * DMODEL + (size_t)h * DKH;

    // scale folds 1/sqrt(dk) and log2(e): softmax done in exp2 domain
    const float qscale = 0.125f * 1.4426950408889634f;

    // --- stage Q (scaled + tf32) then lift to per-warp register fragments ---
    for (int i = tid; i < 128 * 16; i += 256) {
        const int r = i >> 4, c = (i & 15) << 2;
        float4 t = *(const float4*)(Q + base + (size_t)(q0 + r) * DMODEL + c);
        float* d = Ps + r * FA_LDP + c;
        d[0] = __uint_as_float(tf32_rn(t.x * qscale));
        d[1] = __uint_as_float(tf32_rn(t.y * qscale));
        d[2] = __uint_as_float(tf32_rn(t.z * qscale));
        d[3] = __uint_as_float(tf32_rn(t.w * qscale));
    }
    __syncthreads();

    uint32_t qf[8][4];
    {
        const float* pr = Ps + (w * 16 + g) * FA_LDP;
#pragma unroll
        for (int ks = 0; ks < 8; ks++) {
            qf[ks][0] = __float_as_uint(pr[ks * 8 + q]);
            qf[ks][1] = __float_as_uint(pr[8 * FA_LDP + ks * 8 + q]);
            qf[ks][2] = __float_as_uint(pr[ks * 8 + q + 4]);
            qf[ks][3] = __float_as_uint(pr[8 * FA_LDP + ks * 8 + q + 4]);
        }
    }
    __syncthreads();

    float m0 = -1e30f, m1 = -1e30f, l0 = 0.0f, l1 = 0.0f;
    float acc[8][4];
#pragma unroll
    for (int nt = 0; nt < 8; nt++)
#pragma unroll
        for (int r = 0; r < 4; r++) acc[nt][r] = 0.0f;

    const int rmin = q0 + w * 16;        // warp's first query row
    const int rmax = rmin + 15;          // warp's last query row
    const int ntiles = 2 * qb + 2;

    for (int kb = 0; kb < ntiles; kb++) {
        const int kv0 = kb * 64;

        // --- load K, V tiles (tf32-converted) ---
        for (int i = tid; i < 64 * 16; i += 256) {
            const int r = i >> 4, c = (i & 15) << 2;
            float4 t = *(const float4*)(K + base + (size_t)(kv0 + r) * DMODEL + c);
            float* dk = Ks + r * FA_LDK + c;
            dk[0] = __uint_as_float(tf32_rn(t.x));
            dk[1] = __uint_as_float(tf32_rn(t.y));
            dk[2] = __uint_as_float(tf32_rn(t.z));
            dk[3] = __uint_as_float(tf32_rn(t.w));
            float4 u = *(const float4*)(V + base + (size_t)(kv0 + r) * DMODEL + c);
            float* dv = Vs + r * FA_LDV + c;
            dv[0] = __uint_as_float(tf32_rn(u.x));
            dv[1] = __uint_as_float(tf32_rn(u.y));
            dv[2] = __uint_as_float(tf32_rn(u.z));
            dv[3] = __uint_as_float(tf32_rn(u.w));
        }
        __syncthreads();

        if (kv0 <= rmax) {    // warp has at least one unmasked element
            // --- S = Q @ K^T ---
            float sf[8][4];
#pragma unroll
            for (int nt = 0; nt < 8; nt++)
#pragma unroll
                for (int r = 0; r < 4; r++) sf[nt][r] = 0.0f;

#pragma unroll
            for (int ks = 0; ks < 8; ks++) {
#pragma unroll
                for (int nt = 0; nt < 8; nt++) {
                    const float* kr = Ks + (nt * 8 + g) * FA_LDK + ks * 8;
                    const uint32_t b0 = __float_as_uint(kr[q]);
                    const uint32_t b1 = __float_as_uint(kr[q + 4]);
                    mma_tf32(sf[nt][0], sf[nt][1], sf[nt][2], sf[nt][3],
                             qf[ks][0], qf[ks][1], qf[ks][2], qf[ks][3], b0, b1);
                }
            }

            // --- causal mask (diag band only) ---
            if (kv0 + 63 > rmin) {
                const int r0 = rmin + g, r1 = r0 + 8;
#pragma unroll
                for (int nt = 0; nt < 8; nt++) {
                    const int c0 = kv0 + nt * 8 + 2 * q, c1 = c0 + 1;
                    if (c0 > r0) sf[nt][0] = -1e30f;
                    if (c1 > r0) sf[nt][1] = -1e30f;
                    if (c0 > r1) sf[nt][2] = -1e30f;
                    if (c1 > r1) sf[nt][3] = -1e30f;
                }
            }

            // --- online softmax (exp2 domain), rows g / g+8 ---
            float mx0 = -1e30f, mx1 = -1e30f;
#pragma unroll
            for (int nt = 0; nt < 8; nt++) {
                mx0 = fmaxf(mx0, fmaxf(sf[nt][0], sf[nt][1]));
                mx1 = fmaxf(mx1, fmaxf(sf[nt][2], sf[nt][3]));
            }
            mx0 = fmaxf(mx0, __shfl_xor_sync(0xffffffffu, mx0, 1));
            mx0 = fmaxf(mx0, __shfl_xor_sync(0xffffffffu, mx0, 2));
            mx1 = fmaxf(mx1, __shfl_xor_sync(0xffffffffu, mx1, 1));
            mx1 = fmaxf(mx1, __shfl_xor_sync(0xffffffffu, mx1, 2));

            const float mn0 = fmaxf(m0, mx0), mn1 = fmaxf(m1, mx1);
            const float al0 = exp2f(m0 - mn0), al1 = exp2f(m1 - mn1);
            m0 = mn0; m1 = mn1;

            float rs0 = 0.0f, rs1 = 0.0f;
            float* pw = Ps + (w * 16 + g) * FA_LDP;
#pragma unroll
            for (int nt = 0; nt < 8; nt++) {
                const float p00 = exp2f(sf[nt][0] - mn0);
                const float p01 = exp2f(sf[nt][1] - mn0);
                const float p10 = exp2f(sf[nt][2] - mn1);
                const float p11 = exp2f(sf[nt][3] - mn1);
                rs0 += p00 + p01;
                rs1 += p10 + p11;
                const int cc = nt * 8 + 2 * q;
                pw[cc]     = __uint_as_float(tf32_rn(p00));
                pw[cc + 1] = __uint_as_float(tf32_rn(p01));
                pw[8 * FA_LDP + cc]     = __uint_as_float(tf32_rn(p10));
                pw[8 * FA_LDP + cc + 1] = __uint_as_float(tf32_rn(p11));
            }
            rs0 += __shfl_xor_sync(0xffffffffu, rs0, 1);
            rs0 += __shfl_xor_sync(0xffffffffu, rs0, 2);
            rs1 += __shfl_xor_sync(0xffffffffu, rs1, 1);
            rs1 += __shfl_xor_sync(0xffffffffu, rs1, 2);
            l0 = l0 * al0 + rs0;
            l1 = l1 * al1 + rs1;

#pragma unroll
            for (int nt = 0; nt < 8; nt++) {
                acc[nt][0] *= al0; acc[nt][1] *= al0;
                acc[nt][2] *= al1; acc[nt][3] *= al1;
            }
            __syncwarp();   // P rows are warp-private: warp-level ordering only

            // --- O += P @ V ---
#pragma unroll
            for (int ks = 0; ks < 8; ks++) {
                const float* pa = Ps + (w * 16 + g) * FA_LDP + ks * 8;
                const float* pb = pa + 8 * FA_LDP;
                const uint32_t a0 = __float_as_uint(pa[q]);
                const uint32_t a1 = __float_as_uint(pb[q]);
                const uint32_t a2 = __float_as_uint(pa[q + 4]);
                const uint32_t a3 = __float_as_uint(pb[q + 4]);
#pragma unroll
                for (int nt = 0; nt < 8; nt++) {
                    const uint32_t b0 = __float_as_uint(Vs[(ks * 8 + q) * FA_LDV + nt * 8 + g]);
                    const uint32_t b1 = __float_as_uint(Vs[(ks * 8 + 4 + q) * FA_LDV + nt * 8 + g]);
                    mma_tf32(acc[nt][0], acc[nt][1], acc[nt][2], acc[nt][3],
                             a0, a1, a2, a3, b0, b1);
                }
            }
        }
        __syncthreads();   // K/V (and P region) reuse barrier
    }

    // --- epilogue ---
    const float inv0 = 1.0f / l0, inv1 = 1.0f / l1;
    const int r0 = q0 + w * 16 + g;
#pragma unroll
    for (int nt = 0; nt < 8; nt++) {
        const int col = nt * 8 + 2 * q;
        *(float2*)(O + base + (size_t)r0 * DMODEL + col) =
            make_float2(acc[nt][0] * inv0, acc[nt][1] * inv0);
        *(float2*)(O + base + (size_t)(r0 + 8) * DMODEL + col) =
            make_float2(acc[nt][2] * inv1, acc[nt][3] * inv1);
    }
}

// ---------------------------------------------------------------------------
// Launch
// ---------------------------------------------------------------------------
extern "C" void kernel_launch(void* const* d_in, const int* in_sizes, int n_in,
                              void* d_out, int out_size)
{
    const float* x  = (const float*)d_in[0];
    const float* Wq = (const float*)d_in[1];
    const float* Wk = (const float*)d_in[2];
    const float* Wv = (const float*)d_in[3];
    const float* Wo = (const float*)d_in[4];
    float* out = (float*)d_out;

    float *qb, *kb, *vb, *ab;
    cudaGetSymbolAddress((void**)&qb, g_q);
    cudaGetSymbolAddress((void**)&kb, g_k);
    cudaGetSymbolAddress((void**)&vb, g_v);
    cudaGetSymbolAddress((void**)&ab, g_a);

    cudaFuncSetAttribute(gemm_tf32,
                         cudaFuncAttributeMaxDynamicSharedMemorySize, GEMM_SMEM);
    cudaFuncSetAttribute(flash_attn_tc,
                         cudaFuncAttributeMaxDynamicSharedMemorySize, FA_SMEM);

    const dim3 gemm_grid(DMODEL / 128, MROWS / 128);  // (8, 32)
    gemm_tf32<<<gemm_grid, 256, GEMM_SMEM>>>(x, Wq, qb);
    gemm_tf32<<<gemm_grid, 256, GEMM_SMEM>>>(x, Wk, kb);
    gemm_tf32<<<gemm_grid, 256, GEMM_SMEM>>>(x, Wv, vb);

    flash_attn_tc<<<dim3(SEQ / 128, NHEAD, BSZ), 256, FA_SMEM>>>(qb, kb, vb, ab);

    gemm_tf32<<<gemm_grid, 256, GEMM_SMEM>>>(ab, Wo, out);
}

// round 5
// speedup vs baseline: 3.1244x; 1.1390x over previous
#include <cuda_runtime.h>
#include <cstdint>

#define BSZ    2
#define SEQ    2048
#define DMODEL 1024
#define NHEAD  16
#define DKH    64
#define MROWS  (BSZ * SEQ)   // 4096

// Scratch (allocation-free rule: __device__ globals)
__device__ float g_q[MROWS * DMODEL];
__device__ float g_k[MROWS * DMODEL];
__device__ float g_v[MROWS * DMODEL];
__device__ float g_a[MROWS * DMODEL];

// ---------------------------------------------------------------------------
// tf32 helpers (sm_80+ features only — the build targets plain sm_103)
// ---------------------------------------------------------------------------
__device__ __forceinline__ uint32_t tf32_rn(float x) {
    uint32_t u;
    asm("cvt.rna.tf32.f32 %0, %1;" : "=r"(u) : "f"(x));
    return u;
}

__device__ __forceinline__ void mma_tf32(
    float& d0, float& d1, float& d2, float& d3,
    uint32_t a0, uint32_t a1, uint32_t a2, uint32_t a3,
    uint32_t b0, uint32_t b1)
{
    asm volatile(
        "mma.sync.aligned.m16n8k8.row.col.f32.tf32.tf32.f32 "
        "{%0,%1,%2,%3}, {%4,%5,%6,%7}, {%8,%9}, {%0,%1,%2,%3};"
        : "+f"(d0), "+f"(d1), "+f"(d2), "+f"(d3)
        : "r"(a0), "r"(a1), "r"(a2), "r"(a3), "r"(b0), "r"(b1));
}

// ---------------------------------------------------------------------------
// tf32 GEMM NT: C[m,n] = sum_k A[m,k] * W[n,k]   (validated round 3)
// Epilogue: optional scale + tf32 rounding (producer-side rounding for the
// attention consumers; identical rounding points to the round-4 code).
// ---------------------------------------------------------------------------
#define STAGE_FLOATS 8192
#define GEMM_SMEM    (2 * STAGE_FLOATS * 4)   // 65536 B

__global__ __launch_bounds__(256, 1) void gemm_tf32(
    const float* __restrict__ A, const float* __restrict__ W, float* __restrict__ C,
    float oscale, int oround)
{
    extern __shared__ float smf[];

    const int tid  = threadIdx.x;
    const int wid  = tid >> 5;
    const int lane = tid & 31;
    const int wm   = wid & 3;
    const int wn   = wid >> 2;
    const int m0 = blockIdx.y * 128;
    const int n0 = blockIdx.x * 128;

    const int lrow  = tid >> 3;
    const int cbase = (tid & 7) * 4;
    const int ks_w  = cbase >> 3;
    const int half  = (cbase >> 2) & 1;

    float acc[2][8][4];
#pragma unroll
    for (int i = 0; i < 2; i++)
#pragma unroll
        for (int j = 0; j < 8; j++)
#pragma unroll
            for (int r = 0; r < 4; r++) acc[i][j][r] = 0.0f;

    float4 av[4], bv[4];

#pragma unroll
    for (int it = 0; it < 4; it++) {
        av[it] = *(const float4*)(A + (size_t)(m0 + it * 32 + lrow) * DMODEL + cbase);
        bv[it] = *(const float4*)(W + (size_t)(n0 + it * 32 + lrow) * DMODEL + cbase);
    }

    const int NCHUNK = DMODEL / 32;

    for (int s = 0; s < NCHUNK; s++) {
        {
            float* sa = smf + (s & 1) * STAGE_FLOATS;
            float* sb = sa + 4096;
#pragma unroll
            for (int it = 0; it < 4; it++) {
                const int r  = it * 32 + lrow;
                const int mt = r >> 4, rr = r & 15, ga = rr & 7, hi = rr >> 3;
                const int fa = ((ks_w * 8 + mt) * 32 + ga * 4) * 4 + (hi + 2 * half);
                sa[fa + 0]  = __uint_as_float(tf32_rn(av[it].x));
                sa[fa + 4]  = __uint_as_float(tf32_rn(av[it].y));
                sa[fa + 8]  = __uint_as_float(tf32_rn(av[it].z));
                sa[fa + 12] = __uint_as_float(tf32_rn(av[it].w));
                const int nt = r >> 3, gb = r & 7;
                const int fb = ((ks_w * 16 + nt) * 32 + gb * 4) * 2 + half;
                sb[fb + 0] = __uint_as_float(tf32_rn(bv[it].x));
                sb[fb + 2] = __uint_as_float(tf32_rn(bv[it].y));
                sb[fb + 4] = __uint_as_float(tf32_rn(bv[it].z));
                sb[fb + 6] = __uint_as_float(tf32_rn(bv[it].w));
            }
        }
        __syncthreads();

        if (s + 1 < NCHUNK) {
            const int kc = (s + 1) * 32 + cbase;
#pragma unroll
            for (int it = 0; it < 4; it++) {
                av[it] = *(const float4*)(A + (size_t)(m0 + it * 32 + lrow) * DMODEL + kc);
                bv[it] = *(const float4*)(W + (size_t)(n0 + it * 32 + lrow) * DMODEL + kc);
            }
        }

        {
            const float* sa = smf + (s & 1) * STAGE_FLOATS;
            const float* sb = sa + 4096;
#pragma unroll
            for (int ks = 0; ks < 4; ks++) {
                uint4 af[2];
                uint2 bf[8];
#pragma unroll
                for (int mt = 0; mt < 2; mt++)
                    af[mt] = *(const uint4*)(sa + ((ks * 8 + wm * 2 + mt) * 32 + lane) * 4);
#pragma unroll
                for (int nt = 0; nt < 8; nt++)
                    bf[nt] = *(const uint2*)(sb + ((ks * 16 + wn * 8 + nt) * 32 + lane) * 2);
#pragma unroll
                for (int mt = 0; mt < 2; mt++)
#pragma unroll
                    for (int nt = 0; nt < 8; nt++)
                        mma_tf32(acc[mt][nt][0], acc[mt][nt][1],
                                 acc[mt][nt][2], acc[mt][nt][3],
                                 af[mt].x, af[mt].y, af[mt].z, af[mt].w,
                                 bf[nt].x, bf[nt].y);
            }
        }
        __syncthreads();
    }

    const int g = lane >> 2, q = lane & 3;
#pragma unroll
    for (int mt = 0; mt < 2; mt++) {
        const int mrow = m0 + wm * 32 + mt * 16 + g;
#pragma unroll
        for (int nt = 0; nt < 8; nt++) {
            const int ncol = n0 + wn * 64 + nt * 8 + 2 * q;
            float v0 = acc[mt][nt][0], v1 = acc[mt][nt][1];
            float v2 = acc[mt][nt][2], v3 = acc[mt][nt][3];
            if (oround) {
                v0 = __uint_as_float(tf32_rn(v0 * oscale));
                v1 = __uint_as_float(tf32_rn(v1 * oscale));
                v2 = __uint_as_float(tf32_rn(v2 * oscale));
                v3 = __uint_as_float(tf32_rn(v3 * oscale));
            }
            *(float2*)(C + (size_t)mrow * DMODEL + ncol) = make_float2(v0, v1);
            *(float2*)(C + (size_t)(mrow + 8) * DMODEL + ncol) = make_float2(v2, v3);
        }
    }
}

// ---------------------------------------------------------------------------
// Tensor-core flash attention (tf32 mma.sync, causal).
// BQ=128 (8 warps x m16), BKV=64, dk=64. 256 threads.
// Q/K/V arrive pre-scaled + tf32-rounded from the projection GEMM epilogues.
// K/V global loads are register double-buffered to overlap with MMA compute.
// Smem pads: Ps/Ks = 68 (conflict-free (4g+q)), Vs = 72 (conflict-free (8q+g)).
// ---------------------------------------------------------------------------
#define FA_LDP 68
#define FA_LDK 68
#define FA_LDV 72
#define FA_SMEM ((128 * FA_LDP + 64 * FA_LDK + 64 * FA_LDV) * 4)   // 70656 B

__global__ __launch_bounds__(256, 1) void flash_attn_tc(
    const float* __restrict__ Q, const float* __restrict__ K,
    const float* __restrict__ V, float* __restrict__ O)
{
    extern __shared__ float sm[];
    float* Ps = sm;                       // 128 x 68 (Q staging, then P tiles)
    float* Ks = Ps + 128 * FA_LDP;        // 64 x 68
    float* Vs = Ks + 64 * FA_LDK;         // 64 x 72

    const int tid  = threadIdx.x;
    const int w    = tid >> 5;
    const int lane = tid & 31;
    const int g    = lane >> 2;
    const int q    = lane & 3;
    const int qb = blockIdx.x, h = blockIdx.y, b = blockIdx.z;
    const int q0 = qb * 128;
    const size_t base = (size_t)b * SEQ * DMODEL + (size_t)h * DKH;

    const int lr = tid >> 4;              // 0..15 (loader row)
    const int lc = (tid & 15) << 2;       // 0..60 (loader col)

    // --- stage Q (already scaled+rounded) then lift to register fragments ---
    for (int i = tid; i < 128 * 16; i += 256) {
        const int r = i >> 4, c = (i & 15) << 2;
        *(float4*)(Ps + r * FA_LDP + c) =
            *(const float4*)(Q + base + (size_t)(q0 + r) * DMODEL + c);
    }
    __syncthreads();

    uint32_t qf[8][4];
    {
        const float* pr = Ps + (w * 16 + g) * FA_LDP;
#pragma unroll
        for (int ks = 0; ks < 8; ks++) {
            qf[ks][0] = __float_as_uint(pr[ks * 8 + q]);
            qf[ks][1] = __float_as_uint(pr[8 * FA_LDP + ks * 8 + q]);
            qf[ks][2] = __float_as_uint(pr[ks * 8 + q + 4]);
            qf[ks][3] = __float_as_uint(pr[8 * FA_LDP + ks * 8 + q + 4]);
        }
    }
    __syncthreads();

    float m0 = -1e30f, m1 = -1e30f, l0 = 0.0f, l1 = 0.0f;
    float acc[8][4];
#pragma unroll
    for (int nt = 0; nt < 8; nt++)
#pragma unroll
        for (int r = 0; r < 4; r++) acc[nt][r] = 0.0f;

    const int rmin = q0 + w * 16;
    const int rmax = rmin + 15;
    const int ntiles = 2 * qb + 2;

    // --- prologue: prefetch KV tile 0 into registers ---
    float4 kreg[4], vreg[4];
#pragma unroll
    for (int j = 0; j < 4; j++) {
        const size_t roff = base + (size_t)(lr + 16 * j) * DMODEL + lc;
        kreg[j] = *(const float4*)(K + roff);
        vreg[j] = *(const float4*)(V + roff);
    }

    for (int kb = 0; kb < ntiles; kb++) {
        const int kv0 = kb * 64;

        // --- commit staged registers to smem (prev compute done: loop-end barrier) ---
#pragma unroll
        for (int j = 0; j < 4; j++) {
            const int r = lr + 16 * j;
            *(float4*)(Ks + r * FA_LDK + lc) = kreg[j];
            *(float4*)(Vs + r * FA_LDV + lc) = vreg[j];
        }
        __syncthreads();

        // --- prefetch next tile while computing this one ---
        if (kb + 1 < ntiles) {
            const size_t toff = base + (size_t)(kv0 + 64) * DMODEL;
#pragma unroll
            for (int j = 0; j < 4; j++) {
                const size_t roff = toff + (size_t)(lr + 16 * j) * DMODEL + lc;
                kreg[j] = *(const float4*)(K + roff);
                vreg[j] = *(const float4*)(V + roff);
            }
        }

        if (kv0 <= rmax) {    // warp has at least one unmasked element
            // --- S = Q @ K^T ---
            float sf[8][4];
#pragma unroll
            for (int nt = 0; nt < 8; nt++)
#pragma unroll
                for (int r = 0; r < 4; r++) sf[nt][r] = 0.0f;

#pragma unroll
            for (int ks = 0; ks < 8; ks++) {
#pragma unroll
                for (int nt = 0; nt < 8; nt++) {
                    const float* kr = Ks + (nt * 8 + g) * FA_LDK + ks * 8;
                    const uint32_t b0 = __float_as_uint(kr[q]);
                    const uint32_t b1 = __float_as_uint(kr[q + 4]);
                    mma_tf32(sf[nt][0], sf[nt][1], sf[nt][2], sf[nt][3],
                             qf[ks][0], qf[ks][1], qf[ks][2], qf[ks][3], b0, b1);
                }
            }

            // --- causal mask (diag band only) ---
            if (kv0 + 63 > rmin) {
                const int r0 = rmin + g, r1 = r0 + 8;
#pragma unroll
                for (int nt = 0; nt < 8; nt++) {
                    const int c0 = kv0 + nt * 8 + 2 * q, c1 = c0 + 1;
                    if (c0 > r0) sf[nt][0] = -1e30f;
                    if (c1 > r0) sf[nt][1] = -1e30f;
                    if (c0 > r1) sf[nt][2] = -1e30f;
                    if (c1 > r1) sf[nt][3] = -1e30f;
                }
            }

            // --- online softmax (exp2 domain), rows g / g+8 ---
            float mx0 = -1e30f, mx1 = -1e30f;
#pragma unroll
            for (int nt = 0; nt < 8; nt++) {
                mx0 = fmaxf(mx0, fmaxf(sf[nt][0], sf[nt][1]));
                mx1 = fmaxf(mx1, fmaxf(sf[nt][2], sf[nt][3]));
            }
            mx0 = fmaxf(mx0, __shfl_xor_sync(0xffffffffu, mx0, 1));
            mx0 = fmaxf(mx0, __shfl_xor_sync(0xffffffffu, mx0, 2));
            mx1 = fmaxf(mx1, __shfl_xor_sync(0xffffffffu, mx1, 1));
            mx1 = fmaxf(mx1, __shfl_xor_sync(0xffffffffu, mx1, 2));

            const float mn0 = fmaxf(m0, mx0), mn1 = fmaxf(m1, mx1);
            const float al0 = exp2f(m0 - mn0), al1 = exp2f(m1 - mn1);
            m0 = mn0; m1 = mn1;

            float rs0 = 0.0f, rs1 = 0.0f;
            float* pw = Ps + (w * 16 + g) * FA_LDP;
#pragma unroll
            for (int nt = 0; nt < 8; nt++) {
                const float p00 = exp2f(sf[nt][0] - mn0);
                const float p01 = exp2f(sf[nt][1] - mn0);
                const float p10 = exp2f(sf[nt][2] - mn1);
                const float p11 = exp2f(sf[nt][3] - mn1);
                rs0 += p00 + p01;
                rs1 += p10 + p11;
                const int cc = nt * 8 + 2 * q;
                *(float2*)(pw + cc) = make_float2(
                    __uint_as_float(tf32_rn(p00)), __uint_as_float(tf32_rn(p01)));
                *(float2*)(pw + 8 * FA_LDP + cc) = make_float2(
                    __uint_as_float(tf32_rn(p10)), __uint_as_float(tf32_rn(p11)));
            }
            rs0 += __shfl_xor_sync(0xffffffffu, rs0, 1);
            rs0 += __shfl_xor_sync(0xffffffffu, rs0, 2);
            rs1 += __shfl_xor_sync(0xffffffffu, rs1, 1);
            rs1 += __shfl_xor_sync(0xffffffffu, rs1, 2);
            l0 = l0 * al0 + rs0;
            l1 = l1 * al1 + rs1;

#pragma unroll
            for (int nt = 0; nt < 8; nt++) {
                acc[nt][0] *= al0; acc[nt][1] *= al0;
                acc[nt][2] *= al1; acc[nt][3] *= al1;
            }
            __syncwarp();   // P rows are warp-private: warp-level ordering only

            // --- O += P @ V ---
#pragma unroll
            for (int ks = 0; ks < 8; ks++) {
                const float* pa = Ps + (w * 16 + g) * FA_LDP + ks * 8;
                const float* pb = pa + 8 * FA_LDP;
                const uint32_t a0 = __float_as_uint(pa[q]);
                const uint32_t a1 = __float_as_uint(pb[q]);
                const uint32_t a2 = __float_as_uint(pa[q + 4]);
                const uint32_t a3 = __float_as_uint(pb[q + 4]);
#pragma unroll
                for (int nt = 0; nt < 8; nt++) {
                    const uint32_t b0 = __float_as_uint(Vs[(ks * 8 + q) * FA_LDV + nt * 8 + g]);
                    const uint32_t b1 = __float_as_uint(Vs[(ks * 8 + 4 + q) * FA_LDV + nt * 8 + g]);
                    mma_tf32(acc[nt][0], acc[nt][1], acc[nt][2], acc[nt][3],
                             a0, a1, a2, a3, b0, b1);
                }
            }
        }
        __syncthreads();   // K/V (and P region) reuse barrier
    }

    // --- epilogue ---
    const float inv0 = 1.0f / l0, inv1 = 1.0f / l1;
    const int r0 = q0 + w * 16 + g;
#pragma unroll
    for (int nt = 0; nt < 8; nt++) {
        const int col = nt * 8 + 2 * q;
        *(float2*)(O + base + (size_t)r0 * DMODEL + col) =
            make_float2(acc[nt][0] * inv0, acc[nt][1] * inv0);
        *(float2*)(O + base + (size_t)(r0 + 8) * DMODEL + col) =
            make_float2(acc[nt][2] * inv1, acc[nt][3] * inv1);
    }
}

// ---------------------------------------------------------------------------
// Launch
// ---------------------------------------------------------------------------
extern "C" void kernel_launch(void* const* d_in, const int* in_sizes, int n_in,
                              void* d_out, int out_size)
{
    const float* x  = (const float*)d_in[0];
    const float* Wq = (const float*)d_in[1];
    const float* Wk = (const float*)d_in[2];
    const float* Wv = (const float*)d_in[3];
    const float* Wo = (const float*)d_in[4];
    float* out = (float*)d_out;

    float *qb, *kb, *vb, *ab;
    cudaGetSymbolAddress((void**)&qb, g_q);
    cudaGetSymbolAddress((void**)&kb, g_k);
    cudaGetSymbolAddress((void**)&vb, g_v);
    cudaGetSymbolAddress((void**)&ab, g_a);

    cudaFuncSetAttribute(gemm_tf32,
                         cudaFuncAttributeMaxDynamicSharedMemorySize, GEMM_SMEM);
    cudaFuncSetAttribute(flash_attn_tc,
                         cudaFuncAttributeMaxDynamicSharedMemorySize, FA_SMEM);

    // softmax scale folds 1/sqrt(dk) and log2(e) (flash runs in exp2 domain)
    const float qscale = 0.125f * 1.4426950408889634f;

    const dim3 gemm_grid(DMODEL / 128, MROWS / 128);  // (8, 32)
    gemm_tf32<<<gemm_grid, 256, GEMM_SMEM>>>(x, Wq, qb, qscale, 1);
    gemm_tf32<<<gemm_grid, 256, GEMM_SMEM>>>(x, Wk, kb, 1.0f, 1);
    gemm_tf32<<<gemm_grid, 256, GEMM_SMEM>>>(x, Wv, vb, 1.0f, 1);

    flash_attn_tc<<<dim3(SEQ / 128, NHEAD, BSZ), 256, FA_SMEM>>>(qb, kb, vb, ab);

    gemm_tf32<<<gemm_grid, 256, GEMM_SMEM>>>(ab, Wo, out, 1.0f, 0);
}